// round 5
// baseline (speedup 1.0000x reference)
#include <cuda_runtime.h>
#include <cuda_bf16.h>
#include <cstdint>
#include <math.h>

// Problem constants
#define B_   4
#define L_   2048
#define DM   1024
#define H_   16
#define HD   64
#define M_   (B_ * L_)       // 8192 rows
#define EPSC 1e-6f

// ---------------------------------------------------------------------------
// Scratch (allocation-free rule: __device__ globals)
// ---------------------------------------------------------------------------
__device__ float g_Q[(size_t)M_ * DM];
__device__ float g_K[(size_t)M_ * DM];
__device__ float g_V[(size_t)M_ * DM];
__device__ float g_A[(size_t)M_ * DM];   // V_lin (attention output, head-concat)

// ---------------------------------------------------------------------------
// GEMM: C[M,1024] = A[M,1024] @ W[1024,1024] + bias, optional feat = elu(x)+1
// 128x128 tile, BK=16, 256 threads, 8x8 microtile, double-buffered smem.
// ---------------------------------------------------------------------------
__global__ __launch_bounds__(256, 2)
void gemm_bias_kernel(const float* __restrict__ A,
                      const float* __restrict__ W,
                      const float* __restrict__ bias,
                      float* __restrict__ C,
                      int act)
{
    __shared__ float As[2][16][128];
    __shared__ float Bs[2][16][128];

    const int tid = threadIdx.x;
    const int tx = tid & 15;        // 0..15 -> n microtile
    const int ty = tid >> 4;        // 0..15 -> m microtile
    const int m0 = blockIdx.y * 128;
    const int n0 = blockIdx.x * 128;

    // ---- initial tile (kt = 0) straight into buffer 0 ----
    #pragma unroll
    for (int t = 0; t < 2; t++) {
        const int li = tid + t * 256;
        const int r  = li >> 2;         // A row within tile
        const int kq = li & 3;          // which float4 of the 16-wide k slab
        float4 va = *(const float4*)(A + (size_t)(m0 + r) * DM + kq * 4);
        As[0][kq * 4 + 0][r] = va.x;
        As[0][kq * 4 + 1][r] = va.y;
        As[0][kq * 4 + 2][r] = va.z;
        As[0][kq * 4 + 3][r] = va.w;
        const int kk = li >> 5;         // B row within tile
        const int nc = li & 31;         // float4 within the 128-wide n slab
        float4 vb = *(const float4*)(W + (size_t)kk * DM + n0 + nc * 4);
        *(float4*)&Bs[0][kk][nc * 4] = vb;
    }
    __syncthreads();

    float acc[8][8];
    #pragma unroll
    for (int i = 0; i < 8; i++)
        #pragma unroll
        for (int j = 0; j < 8; j++) acc[i][j] = 0.f;

    float4 pa[2], pb[2];

    const int KT = DM / 16;  // 64
    for (int kt = 0; kt < KT; kt++) {
        const int buf = kt & 1;

        // prefetch next tile to registers
        if (kt < KT - 1) {
            #pragma unroll
            for (int t = 0; t < 2; t++) {
                const int li = tid + t * 256;
                const int r  = li >> 2;
                const int kq = li & 3;
                pa[t] = *(const float4*)(A + (size_t)(m0 + r) * DM + (kt + 1) * 16 + kq * 4);
                const int kk = li >> 5;
                const int nc = li & 31;
                pb[t] = *(const float4*)(W + (size_t)((kt + 1) * 16 + kk) * DM + n0 + nc * 4);
            }
        }

        // compute on current buffer
        #pragma unroll
        for (int kk = 0; kk < 16; kk++) {
            float af[8], bf[8];
            #pragma unroll
            for (int j = 0; j < 8; j++) af[j] = As[buf][kk][ty * 8 + j];
            #pragma unroll
            for (int j = 0; j < 8; j++) bf[j] = Bs[buf][kk][tx * 8 + j];
            #pragma unroll
            for (int i = 0; i < 8; i++)
                #pragma unroll
                for (int j = 0; j < 8; j++)
                    acc[i][j] += af[i] * bf[j];
        }

        // drain prefetch registers into the other buffer
        if (kt < KT - 1) {
            const int nb = buf ^ 1;
            #pragma unroll
            for (int t = 0; t < 2; t++) {
                const int li = tid + t * 256;
                const int r  = li >> 2;
                const int kq = li & 3;
                As[nb][kq * 4 + 0][r] = pa[t].x;
                As[nb][kq * 4 + 1][r] = pa[t].y;
                As[nb][kq * 4 + 2][r] = pa[t].z;
                As[nb][kq * 4 + 3][r] = pa[t].w;
                const int kk = li >> 5;
                const int nc = li & 31;
                *(float4*)&Bs[nb][kk][nc * 4] = pb[t];
            }
        }
        __syncthreads();
    }

    // epilogue: bias (+ feat), vectorized stores
    float bv[8];
    #pragma unroll
    for (int j = 0; j < 8; j++) bv[j] = bias[n0 + tx * 8 + j];

    #pragma unroll
    for (int i = 0; i < 8; i++) {
        float* crow = C + (size_t)(m0 + ty * 8 + i) * DM + n0 + tx * 8;
        float o[8];
        #pragma unroll
        for (int j = 0; j < 8; j++) {
            float v = acc[i][j] + bv[j];
            if (act) v = (v > 0.f) ? (v + 1.f) : expf(v);  // elu(x)+1
            o[j] = v;
        }
        *(float4*)(crow + 0) = make_float4(o[0], o[1], o[2], o[3]);
        *(float4*)(crow + 4) = make_float4(o[4], o[5], o[6], o[7]);
    }
}

// ---------------------------------------------------------------------------
// Causal linear-attention scan. One CTA per (b,h); 512 threads.
// Thread (a = tid>>3, cg = tid&7) owns S[a][cg*8 .. cg*8+7] in registers.
// Per step: S += k[a]*v[c]; num[a] = sum_c S[a][c]*q[c] (swapped-einsum);
// out[a] = num[a] / (q[a]*Z[a] + eps), Z[a] += k[a].
// q/k/v streamed through a 16-stage cp.async pipeline to hide DRAM latency.
// ---------------------------------------------------------------------------
#define NSTAGE 16

__global__ __launch_bounds__(512, 1)
void attn_scan_kernel(const float* __restrict__ Q,
                      const float* __restrict__ K,
                      const float* __restrict__ V,
                      float* __restrict__ O)
{
    __shared__ float sh[NSTAGE][3][64];   // [stage][q/k/v][64]

    const int b = blockIdx.x >> 4;
    const int h = blockIdx.x & 15;
    const int tid = threadIdx.x;
    const size_t base = (size_t)b * L_ * DM + (size_t)h * HD;

    const int role  = tid >> 4;   // 0=q,1=k,2=v for tid<48
    const int lane4 = tid & 15;   // float4 index 0..15

    // prologue: stages 0..NSTAGE-2
    for (int s = 0; s < NSTAGE - 1; s++) {
        if (tid < 48) {
            const float* src = (role == 0) ? Q : (role == 1) ? K : V;
            const float* g = src + base + (size_t)s * DM + lane4 * 4;
            unsigned saddr = (unsigned)__cvta_generic_to_shared(&sh[s][role][lane4 * 4]);
            asm volatile("cp.async.ca.shared.global [%0], [%1], 16;\n"
                         :: "r"(saddr), "l"(g));
        }
        asm volatile("cp.async.commit_group;\n");
    }

    const int a  = tid >> 3;
    const int cg = tid & 7;
    const int c0 = cg * 8;

    float S[8];
    #pragma unroll
    for (int j = 0; j < 8; j++) S[j] = 0.f;
    float Z = 0.f;

    for (int i = 0; i < L_; i++) {
        // stage i ready for the issuing thread, barrier publishes it to all
        asm volatile("cp.async.wait_group %0;\n" :: "n"(NSTAGE - 2));
        __syncthreads();

        // refill stage (i-1)%NSTAGE with step i+NSTAGE-1 (consumed last iter,
        // barrier above guarantees everyone is done with it)
        const int pf = i + NSTAGE - 1;
        if (pf < L_ && tid < 48) {
            const float* src = (role == 0) ? Q : (role == 1) ? K : V;
            const float* g = src + base + (size_t)pf * DM + lane4 * 4;
            unsigned saddr =
                (unsigned)__cvta_generic_to_shared(&sh[pf % NSTAGE][role][lane4 * 4]);
            asm volatile("cp.async.ca.shared.global [%0], [%1], 16;\n"
                         :: "r"(saddr), "l"(g));
        }
        asm volatile("cp.async.commit_group;\n");  // uniform: keeps group counts aligned

        const int st = i % NSTAGE;
        const float ka = sh[st][1][a];

        const float4 q0 = *(const float4*)&sh[st][0][c0];
        const float4 q1 = *(const float4*)&sh[st][0][c0 + 4];
        const float4 v0 = *(const float4*)&sh[st][2][c0];
        const float4 v1 = *(const float4*)&sh[st][2][c0 + 4];

        float num = 0.f;
        S[0] += ka * v0.x; num += S[0] * q0.x;
        S[1] += ka * v0.y; num += S[1] * q0.y;
        S[2] += ka * v0.z; num += S[2] * q0.z;
        S[3] += ka * v0.w; num += S[3] * q0.w;
        S[4] += ka * v1.x; num += S[4] * q1.x;
        S[5] += ka * v1.y; num += S[5] * q1.y;
        S[6] += ka * v1.z; num += S[6] * q1.z;
        S[7] += ka * v1.w; num += S[7] * q1.w;

        // reduce across the 8 lanes of this row-group
        num += __shfl_xor_sync(0xffffffffu, num, 1);
        num += __shfl_xor_sync(0xffffffffu, num, 2);
        num += __shfl_xor_sync(0xffffffffu, num, 4);

        if (cg == 0) {
            Z += ka;
            const float qa = sh[st][0][a];
            O[base + (size_t)i * DM + a] = num / (qa * Z + EPSC);
        }
    }
}

// ---------------------------------------------------------------------------
// kernel_launch
// Inputs: 0 queries, 1 keys, 2 values, 3 Wq, 4 bq, 5 Wk, 6 bk, 7 Wv, 8 bv,
//         9 Wo, 10 bo. Output: [8192,1024] fp32.
// ---------------------------------------------------------------------------
extern "C" void kernel_launch(void* const* d_in, const int* in_sizes, int n_in,
                              void* d_out, int out_size)
{
    const float* queries = (const float*)d_in[0];
    const float* keys    = (const float*)d_in[1];
    const float* values  = (const float*)d_in[2];
    const float* Wq = (const float*)d_in[3];
    const float* bq = (const float*)d_in[4];
    const float* Wk = (const float*)d_in[5];
    const float* bk = (const float*)d_in[6];
    const float* Wv = (const float*)d_in[7];
    const float* bv = (const float*)d_in[8];
    const float* Wo = (const float*)d_in[9];
    const float* bo = (const float*)d_in[10];
    float* out = (float*)d_out;

    float *pQ, *pK, *pV, *pA;
    cudaGetSymbolAddress((void**)&pQ, g_Q);
    cudaGetSymbolAddress((void**)&pK, g_K);
    cudaGetSymbolAddress((void**)&pV, g_V);
    cudaGetSymbolAddress((void**)&pA, g_A);

    dim3 gemm_grid(DM / 128, M_ / 128);   // (8, 64)
    dim3 gemm_block(256);

    // projections (+ feat on Q,K)
    gemm_bias_kernel<<<gemm_grid, gemm_block>>>(queries, Wq, bq, pQ, 1);
    gemm_bias_kernel<<<gemm_grid, gemm_block>>>(keys,    Wk, bk, pK, 1);
    gemm_bias_kernel<<<gemm_grid, gemm_block>>>(values,  Wv, bv, pV, 0);

    // causal linear attention scan
    attn_scan_kernel<<<B_ * H_, 512>>>(pQ, pK, pV, pA);

    // output projection
    gemm_bias_kernel<<<gemm_grid, gemm_block>>>(pA, Wo, bo, out, 0);
}

// round 6
// speedup vs baseline: 1.2325x; 1.2325x over previous
#include <cuda_runtime.h>
#include <cuda_bf16.h>
#include <cstdint>
#include <math.h>

// Problem constants
#define B_   4
#define L_   2048
#define DM   1024
#define H_   16
#define HD   64
#define M_   (B_ * L_)       // 8192 rows
#define EPSC 1e-6f
#define CH   64              // scan chunk length
#define NCH  (L_ / CH)       // 32 chunks

// ---------------------------------------------------------------------------
// Scratch (allocation-free rule: __device__ globals)
// ---------------------------------------------------------------------------
__device__ float g_Q[(size_t)M_ * DM];
__device__ float g_K[(size_t)M_ * DM];
__device__ float g_V[(size_t)M_ * DM];
__device__ float g_A[(size_t)M_ * DM];                 // attention output
__device__ float g_S[(size_t)B_ * H_ * NCH * HD * HD]; // chunk S sums -> exclusive prefix
__device__ float g_Z[(size_t)B_ * H_ * NCH * HD];      // chunk Z sums -> exclusive prefix

// ---------------------------------------------------------------------------
// Packed fp32x2 helpers (Blackwell FFMA2 via PTX — not emitted by ptxas from C++)
// ---------------------------------------------------------------------------
__device__ __forceinline__ void ffma2(unsigned long long& d,
                                      unsigned long long a,
                                      unsigned long long b) {
    asm("fma.rn.f32x2 %0, %1, %2, %0;" : "+l"(d) : "l"(a), "l"(b));
}
__device__ __forceinline__ void unpack2(float& lo, float& hi, unsigned long long v) {
    asm("mov.b64 {%0, %1}, %2;" : "=f"(lo), "=f"(hi) : "l"(v));
}

// ---------------------------------------------------------------------------
// GEMM: C[M,1024] = A[M,1024] @ W[1024,1024] + bias, optional feat = elu(x)+1
// 128x128 tile, BK=16, 256 threads, 8x8 microtile.
// A held DUPLICATED in smem so each 64-bit LDS yields {a,a}; inner loop is
// 32x fma.rn.f32x2 per k-step (64 FMA) instead of 64 scalar FFMA.
// ---------------------------------------------------------------------------
__global__ __launch_bounds__(256, 2)
void gemm_bias_kernel(const float* __restrict__ A,
                      const float* __restrict__ W,
                      const float* __restrict__ bias,
                      float* __restrict__ C,
                      int act)
{
    __shared__ float AsD[2][16][256];   // duplicated A: [kk][2r]=[kk][2r+1]=A
    __shared__ float Bs[2][16][128];

    const int tid = threadIdx.x;
    const int tx = tid & 15;        // n microtile
    const int ty = tid >> 4;        // m microtile
    const int m0 = blockIdx.y * 128;
    const int n0 = blockIdx.x * 128;

    // ---- initial tile (kt = 0) into buffer 0 ----
    #pragma unroll
    for (int t = 0; t < 2; t++) {
        const int li = tid + t * 256;
        const int r  = li >> 2;
        const int kq = li & 3;
        float4 va = *(const float4*)(A + (size_t)(m0 + r) * DM + kq * 4);
        #pragma unroll
        for (int e = 0; e < 4; e++) {
            float v = (&va.x)[e];
            AsD[0][kq * 4 + e][2 * r]     = v;
            AsD[0][kq * 4 + e][2 * r + 1] = v;
        }
        const int kk = li >> 5;
        const int nc = li & 31;
        float4 vb = *(const float4*)(W + (size_t)kk * DM + n0 + nc * 4);
        *(float4*)&Bs[0][kk][nc * 4] = vb;
    }
    __syncthreads();

    unsigned long long acc2[8][4];
    #pragma unroll
    for (int i = 0; i < 8; i++)
        #pragma unroll
        for (int j = 0; j < 4; j++) acc2[i][j] = 0ULL;

    float4 pa[2], pb[2];

    const int KT = DM / 16;  // 64
    for (int kt = 0; kt < KT; kt++) {
        const int buf = kt & 1;

        // prefetch next tile to registers
        if (kt < KT - 1) {
            #pragma unroll
            for (int t = 0; t < 2; t++) {
                const int li = tid + t * 256;
                const int r  = li >> 2;
                const int kq = li & 3;
                pa[t] = *(const float4*)(A + (size_t)(m0 + r) * DM + (kt + 1) * 16 + kq * 4);
                const int kk = li >> 5;
                const int nc = li & 31;
                pb[t] = *(const float4*)(W + (size_t)((kt + 1) * 16 + kk) * DM + n0 + nc * 4);
            }
        }

        // compute on current buffer: FFMA2 inner loop
        #pragma unroll
        for (int kk = 0; kk < 16; kk++) {
            const unsigned long long* ap =
                (const unsigned long long*)&AsD[buf][kk][ty * 16];
            const unsigned long long* bp =
                (const unsigned long long*)&Bs[buf][kk][tx * 8];
            unsigned long long a2[8], b2[4];
            #pragma unroll
            for (int i = 0; i < 8; i++) a2[i] = ap[i];
            #pragma unroll
            for (int j = 0; j < 4; j++) b2[j] = bp[j];
            #pragma unroll
            for (int i = 0; i < 8; i++)
                #pragma unroll
                for (int j = 0; j < 4; j++)
                    ffma2(acc2[i][j], a2[i], b2[j]);
        }

        // drain prefetch registers into the other buffer
        if (kt < KT - 1) {
            const int nb = buf ^ 1;
            #pragma unroll
            for (int t = 0; t < 2; t++) {
                const int li = tid + t * 256;
                const int r  = li >> 2;
                const int kq = li & 3;
                #pragma unroll
                for (int e = 0; e < 4; e++) {
                    float v = (&pa[t].x)[e];
                    AsD[nb][kq * 4 + e][2 * r]     = v;
                    AsD[nb][kq * 4 + e][2 * r + 1] = v;
                }
                const int kk = li >> 5;
                const int nc = li & 31;
                *(float4*)&Bs[nb][kk][nc * 4] = pb[t];
            }
        }
        __syncthreads();
    }

    // epilogue: bias (+ feat), vectorized stores
    float bv[8];
    #pragma unroll
    for (int j = 0; j < 8; j++) bv[j] = bias[n0 + tx * 8 + j];

    #pragma unroll
    for (int i = 0; i < 8; i++) {
        float* crow = C + (size_t)(m0 + ty * 8 + i) * DM + n0 + tx * 8;
        float o[8];
        #pragma unroll
        for (int j2 = 0; j2 < 4; j2++) {
            float lo, hi;
            unpack2(lo, hi, acc2[i][j2]);
            o[2 * j2 + 0] = lo + bv[2 * j2 + 0];
            o[2 * j2 + 1] = hi + bv[2 * j2 + 1];
        }
        if (act) {
            #pragma unroll
            for (int j = 0; j < 8; j++)
                o[j] = (o[j] > 0.f) ? (o[j] + 1.f) : expf(o[j]);  // elu(x)+1
        }
        *(float4*)(crow + 0) = make_float4(o[0], o[1], o[2], o[3]);
        *(float4*)(crow + 4) = make_float4(o[4], o[5], o[6], o[7]);
    }
}

// ---------------------------------------------------------------------------
// Chunked linear-attention scan.
//
// For chunk ch of head (b,h):
//   S_ch[c][a]  = sum_{j in ch} k_j[a] * v_j[c]     (kernel A)
//   Z_ch[a]     = sum_{j in ch} k_j[a]
// exclusive prefix over chunks (kernel B), then per chunk (kernel C):
//   G[i][j]     = q_i . v_j  (j <= i)
//   num[i][a]   = sum_j G[i][j] k_j[a] + sum_c Sprev[c][a] q_i[c]
//   Zc[i][a]    = Zprev[a] + sum_{j<=i} k_j[a]
//   out[i][a]   = num[i][a] / (q_i[a] * Zc[i][a] + eps)
// ---------------------------------------------------------------------------

// Kernel A: per-chunk S and Z sums. grid (NCH, B*H), 256 threads.
__global__ __launch_bounds__(256, 2)
void attn_chunk_sums(const float* __restrict__ K,
                     const float* __restrict__ V,
                     float* __restrict__ S,
                     float* __restrict__ Z)
{
    __shared__ float sK[64][64];
    __shared__ float sV[64][64];

    const int ch = blockIdx.x, bh = blockIdx.y;
    const int b = bh >> 4, h = bh & 15;
    const size_t base = (size_t)b * L_ * DM + (size_t)h * HD + (size_t)ch * CH * DM;
    const int tid = threadIdx.x;
    const int tx = tid & 15, ty = tid >> 4;

    #pragma unroll
    for (int it = 0; it < 4; it++) {
        const int r = ty + it * 16;
        *(float4*)&sK[r][tx * 4] = *(const float4*)(K + base + (size_t)r * DM + tx * 4);
        *(float4*)&sV[r][tx * 4] = *(const float4*)(V + base + (size_t)r * DM + tx * 4);
    }
    __syncthreads();

    // thread owns (c = ty*4.., a = tx*4..) tile of S[c][a]
    float acc[4][4];
    #pragma unroll
    for (int i = 0; i < 4; i++)
        #pragma unroll
        for (int j = 0; j < 4; j++) acc[i][j] = 0.f;

    #pragma unroll 4
    for (int j = 0; j < 64; j++) {
        float4 vc = *(const float4*)&sV[j][ty * 4];   // broadcast across tx
        float4 ka = *(const float4*)&sK[j][tx * 4];
        #pragma unroll
        for (int ci = 0; ci < 4; ci++)
            #pragma unroll
            for (int ai = 0; ai < 4; ai++)
                acc[ci][ai] += (&vc.x)[ci] * (&ka.x)[ai];
    }

    float* sout = S + ((size_t)bh * NCH + ch) * (HD * HD);
    #pragma unroll
    for (int ci = 0; ci < 4; ci++)
        *(float4*)(sout + (size_t)(ty * 4 + ci) * HD + tx * 4) =
            make_float4(acc[ci][0], acc[ci][1], acc[ci][2], acc[ci][3]);

    if (tid < 64) {
        float s = 0.f;
        #pragma unroll 8
        for (int j = 0; j < 64; j++) s += sK[j][tid];
        Z[((size_t)bh * NCH + ch) * HD + tid] = s;
    }
}

// Kernel B: exclusive prefix over chunks of S and Z, per (b,h). grid 64, 512 thr.
__global__ __launch_bounds__(512, 1)
void attn_prefix(float* __restrict__ S, float* __restrict__ Z)
{
    const int bh = blockIdx.x;
    const int tid = threadIdx.x;
    const size_t sb = (size_t)bh * NCH * (HD * HD);

    float run[8];
    #pragma unroll
    for (int u = 0; u < 8; u++) run[u] = 0.f;

    for (int ch = 0; ch < NCH; ch++) {
        #pragma unroll
        for (int u = 0; u < 8; u++) {
            const size_t idx = sb + (size_t)ch * (HD * HD) + tid + u * 512;
            float t = S[idx];
            S[idx] = run[u];
            run[u] += t;
        }
    }

    if (tid < 64) {
        const size_t zb = (size_t)bh * NCH * HD;
        float rz = 0.f;
        for (int ch = 0; ch < NCH; ch++) {
            float t = Z[zb + (size_t)ch * HD + tid];
            Z[zb + (size_t)ch * HD + tid] = rz;
            rz += t;
        }
    }
}

// Skewed transpose column helper: element X[r][c] stored at sXT[c][skcol(r,c)]
__device__ __forceinline__ int skcol(int r, int c) {
    return 4 * (((r >> 2) + c) & 15) + (r & 3);
}

// Kernel C: per-chunk outputs. grid (NCH, B*H), 256 threads, 48KB smem.
__global__ __launch_bounds__(256, 2)
void attn_chunk_out(const float* __restrict__ Q,
                    const float* __restrict__ K,
                    const float* __restrict__ V,
                    const float* __restrict__ Sp,
                    const float* __restrict__ Zp,
                    float* __restrict__ O)
{
    __shared__ float sQT[64][64];   // Q transposed + skewed: [c][skcol(i,c)]
    __shared__ float sKV[64][64];   // V transposed+skewed, then K row-major
    __shared__ float sW[64][64];    // G -> SpT -> Zcum

    const int ch = blockIdx.x, bh = blockIdx.y;
    const int b = bh >> 4, h = bh & 15;
    const size_t base = (size_t)b * L_ * DM + (size_t)h * HD + (size_t)ch * CH * DM;
    const int tid = threadIdx.x;
    const int tx = tid & 15, ty = tid >> 4;

    // load Q, V transposed + skewed
    #pragma unroll
    for (int it = 0; it < 4; it++) {
        const int r = ty + it * 16;
        float4 q = *(const float4*)(Q + base + (size_t)r * DM + tx * 4);
        float4 v = *(const float4*)(V + base + (size_t)r * DM + tx * 4);
        #pragma unroll
        for (int u = 0; u < 4; u++) {
            const int c = tx * 4 + u;
            sQT[c][skcol(r, c)] = (&q.x)[u];
            sKV[c][skcol(r, c)] = (&v.x)[u];
        }
    }
    __syncthreads();

    // Phase A: G[i][j] = q_i . v_j, masked j<=i, into sW. (i-blk=ty, j-blk=tx)
    {
        float g[4][4];
        #pragma unroll
        for (int i = 0; i < 4; i++)
            #pragma unroll
            for (int j = 0; j < 4; j++) g[i][j] = 0.f;

        #pragma unroll 4
        for (int c = 0; c < 64; c++) {
            float4 qi = *(const float4*)&sQT[c][4 * ((ty + c) & 15)];
            float4 vj = *(const float4*)&sKV[c][4 * ((tx + c) & 15)];
            #pragma unroll
            for (int ii = 0; ii < 4; ii++)
                #pragma unroll
                for (int jj = 0; jj < 4; jj++)
                    g[ii][jj] += (&qi.x)[ii] * (&vj.x)[jj];
        }
        #pragma unroll
        for (int ii = 0; ii < 4; ii++) {
            const int i = ty * 4 + ii;
            #pragma unroll
            for (int jj = 0; jj < 4; jj++) {
                const int j = tx * 4 + jj;
                sW[i][j] = (j <= i) ? g[ii][jj] : 0.f;
            }
        }
    }
    __syncthreads();

    // reload K row-major over sKV (VT is dead)
    #pragma unroll
    for (int it = 0; it < 4; it++) {
        const int r = ty + it * 16;
        *(float4*)&sKV[r][tx * 4] = *(const float4*)(K + base + (size_t)r * DM + tx * 4);
    }
    __syncthreads();

    // Phase B: num[i][a] += sum_j G[i][j] * K[j][a]   (i-blk=ty, a-blk=tx)
    float acc[4][4];
    #pragma unroll
    for (int i = 0; i < 4; i++)
        #pragma unroll
        for (int j = 0; j < 4; j++) acc[i][j] = 0.f;

    #pragma unroll 4
    for (int j = 0; j < 64; j++) {
        float gi[4];
        #pragma unroll
        for (int ii = 0; ii < 4; ii++) gi[ii] = sW[ty * 4 + ii][j];  // 2-addr bcast
        float4 ka = *(const float4*)&sKV[j][tx * 4];
        #pragma unroll
        for (int ii = 0; ii < 4; ii++)
            #pragma unroll
            for (int aa = 0; aa < 4; aa++)
                acc[ii][aa] += gi[ii] * (&ka.x)[aa];
    }
    __syncthreads();

    // load exclusive-prefix S (layout [c][a]) into sW
    {
        const float* sp = Sp + ((size_t)bh * NCH + ch) * (HD * HD);
        #pragma unroll
        for (int it = 0; it < 4; it++) {
            const int r = ty + it * 16;
            *(float4*)&sW[r][tx * 4] = *(const float4*)(sp + (size_t)r * HD + tx * 4);
        }
    }
    __syncthreads();

    // Phase C: num[i][a] += sum_c Sprev[c][a] * q_i[c]
    #pragma unroll 4
    for (int c = 0; c < 64; c++) {
        float4 qi = *(const float4*)&sQT[c][4 * ((ty + c) & 15)];
        float4 sa = *(const float4*)&sW[c][tx * 4];
        #pragma unroll
        for (int ii = 0; ii < 4; ii++)
            #pragma unroll
            for (int aa = 0; aa < 4; aa++)
                acc[ii][aa] += (&qi.x)[ii] * (&sa.x)[aa];
    }
    __syncthreads();

    // Phase D: inclusive Z cumsum (+ chunk-exclusive prefix) into sW
    if (tid < 64) {
        const int a = tid;
        float run = Zp[((size_t)bh * NCH + ch) * HD + a];
        for (int i = 0; i < 64; i++) {
            run += sKV[i][a];
            sW[i][a] = run;
        }
    }
    __syncthreads();

    // Phase E: out[i][a] = num / (q_i[a] * Z_i[a] + eps)
    #pragma unroll
    for (int ii = 0; ii < 4; ii++) {
        const int i = ty * 4 + ii;
        float4 z = *(const float4*)&sW[i][tx * 4];
        float o[4];
        #pragma unroll
        for (int aa = 0; aa < 4; aa++) {
            const int a = tx * 4 + aa;
            const float qv = sQT[a][skcol(i, a)];
            o[aa] = acc[ii][aa] / (qv * (&z.x)[aa] + EPSC);
        }
        *(float4*)(O + base + (size_t)i * DM + tx * 4) =
            make_float4(o[0], o[1], o[2], o[3]);
    }
}

// ---------------------------------------------------------------------------
// kernel_launch
// Inputs: 0 queries, 1 keys, 2 values, 3 Wq, 4 bq, 5 Wk, 6 bk, 7 Wv, 8 bv,
//         9 Wo, 10 bo. Output: [8192,1024] fp32.
// ---------------------------------------------------------------------------
extern "C" void kernel_launch(void* const* d_in, const int* in_sizes, int n_in,
                              void* d_out, int out_size)
{
    const float* queries = (const float*)d_in[0];
    const float* keys    = (const float*)d_in[1];
    const float* values  = (const float*)d_in[2];
    const float* Wq = (const float*)d_in[3];
    const float* bq = (const float*)d_in[4];
    const float* Wk = (const float*)d_in[5];
    const float* bk = (const float*)d_in[6];
    const float* Wv = (const float*)d_in[7];
    const float* bv = (const float*)d_in[8];
    const float* Wo = (const float*)d_in[9];
    const float* bo = (const float*)d_in[10];
    float* out = (float*)d_out;

    float *pQ, *pK, *pV, *pA, *pS, *pZ;
    cudaGetSymbolAddress((void**)&pQ, g_Q);
    cudaGetSymbolAddress((void**)&pK, g_K);
    cudaGetSymbolAddress((void**)&pV, g_V);
    cudaGetSymbolAddress((void**)&pA, g_A);
    cudaGetSymbolAddress((void**)&pS, g_S);
    cudaGetSymbolAddress((void**)&pZ, g_Z);

    dim3 gemm_grid(DM / 128, M_ / 128);   // (8, 64)

    // projections (+ feat on Q,K)
    gemm_bias_kernel<<<gemm_grid, 256>>>(queries, Wq, bq, pQ, 1);
    gemm_bias_kernel<<<gemm_grid, 256>>>(keys,    Wk, bk, pK, 1);
    gemm_bias_kernel<<<gemm_grid, 256>>>(values,  Wv, bv, pV, 0);

    // chunked causal linear attention
    dim3 chunk_grid(NCH, B_ * H_);        // (32, 64)
    attn_chunk_sums<<<chunk_grid, 256>>>(pK, pV, pS, pZ);
    attn_prefix<<<B_ * H_, 512>>>(pS, pZ);
    attn_chunk_out<<<chunk_grid, 256>>>(pQ, pK, pV, pS, pZ, pA);

    // output projection
    gemm_bias_kernel<<<gemm_grid, 256>>>(pA, Wo, bo, out, 0);
}

// round 8
// speedup vs baseline: 3.0527x; 2.4768x over previous
#include <cuda_runtime.h>
#include <cuda_bf16.h>
#include <cstdint>
#include <math.h>

// Problem constants
#define B_   4
#define L_   2048
#define DM   1024
#define H_   16
#define HD   64
#define M_   (B_ * L_)       // 8192 rows
#define EPSC 1e-6f
#define CH   64              // scan chunk length
#define NCH  (L_ / CH)       // 32 chunks

// GEMM constants
#define KC        64                  // bf16 K elems per chunk (128 B rows)
#define KCHUNKS   (DM / KC)           // 16
#define TILE_B    16384               // 128-row x 128-byte tile
#define STG_B     (4 * TILE_B)        // Ahi, Alo, Bhi, Blo
#define SMEM_GEMM (2 * STG_B)         // double buffer = 128 KB

// ---------------------------------------------------------------------------
// Scratch (allocation-free rule: __device__ globals)
// ---------------------------------------------------------------------------
__device__ float g_Q[(size_t)M_ * DM];
__device__ float g_K[(size_t)M_ * DM];
__device__ float g_V[(size_t)M_ * DM];
__device__ float g_A[(size_t)M_ * DM];                 // attention output
__device__ float g_S[(size_t)B_ * H_ * NCH * HD * HD]; // chunk S sums -> prefix
__device__ float g_Z[(size_t)B_ * H_ * NCH * HD];      // chunk Z sums -> prefix
__device__ __nv_bfloat16 g_Ahi[(size_t)M_ * DM];
__device__ __nv_bfloat16 g_Alo[(size_t)M_ * DM];
__device__ __nv_bfloat16 g_Whi[(size_t)DM * DM];       // [N, K] (transposed W)
__device__ __nv_bfloat16 g_Wlo[(size_t)DM * DM];

// ---------------------------------------------------------------------------
// PTX helpers (base-target sm_103-safe: cp.async, ldmatrix, mma.sync only)
// ---------------------------------------------------------------------------
__device__ __forceinline__ uint32_t smem_u32(const void* p) {
    uint32_t a;
    asm("{ .reg .u64 t; cvta.to.shared.u64 t, %1; cvt.u32.u64 %0, t; }" : "=r"(a) : "l"(p));
    return a;
}
__device__ __forceinline__ void cp16(uint32_t saddr, const void* g) {
    asm volatile("cp.async.cg.shared.global [%0], [%1], 16;\n" :: "r"(saddr), "l"(g));
}
#define CP_COMMIT() asm volatile("cp.async.commit_group;\n")
#define CP_WAIT0()  asm volatile("cp.async.wait_group 0;\n")
#define CP_WAIT1()  asm volatile("cp.async.wait_group 1;\n")

__device__ __forceinline__ void ldsm4(uint32_t* r, uint32_t addr) {
    asm volatile("ldmatrix.sync.aligned.m8n8.x4.shared.b16 {%0,%1,%2,%3}, [%4];"
                 : "=r"(r[0]), "=r"(r[1]), "=r"(r[2]), "=r"(r[3]) : "r"(addr));
}
__device__ __forceinline__ void mma16816(float* d, const uint32_t* a,
                                         uint32_t b0, uint32_t b1) {
    asm volatile(
        "mma.sync.aligned.m16n8k16.row.col.f32.bf16.bf16.f32 "
        "{%0,%1,%2,%3}, {%4,%5,%6,%7}, {%8,%9}, {%0,%1,%2,%3};"
        : "+f"(d[0]), "+f"(d[1]), "+f"(d[2]), "+f"(d[3])
        : "r"(a[0]), "r"(a[1]), "r"(a[2]), "r"(a[3]), "r"(b0), "r"(b1));
}

// SW128 swizzle address within a 128-row x 128-byte tile
__device__ __forceinline__ uint32_t swaddr(uint32_t tilebase, int row, int cbyte) {
    uint32_t off = ((uint32_t)(row >> 3) << 10) + ((uint32_t)(row & 7) << 7)
                 + (uint32_t)cbyte;
    return tilebase + (off ^ ((off >> 3) & 0x70u));
}

// ---------------------------------------------------------------------------
// Split converters: x -> (bf16 hi, bf16 lo)
// ---------------------------------------------------------------------------
__global__ __launch_bounds__(256)
void conv_split_kernel(const float* __restrict__ X,
                       __nv_bfloat16* __restrict__ Hi,
                       __nv_bfloat16* __restrict__ Lo)
{
    const size_t i = ((size_t)blockIdx.x * 256 + threadIdx.x) * 4;
    float4 v = *(const float4*)(X + i);
    unsigned short h[4], l[4];
    #pragma unroll
    for (int e = 0; e < 4; e++) {
        float x = (&v.x)[e];
        __nv_bfloat16 hb = __float2bfloat16(x);
        __nv_bfloat16 lb = __float2bfloat16(x - __bfloat162float(hb));
        h[e] = __bfloat16_as_ushort(hb);
        l[e] = __bfloat16_as_ushort(lb);
    }
    uint2 uh, ul;
    uh.x = (uint32_t)h[0] | ((uint32_t)h[1] << 16);
    uh.y = (uint32_t)h[2] | ((uint32_t)h[3] << 16);
    ul.x = (uint32_t)l[0] | ((uint32_t)l[1] << 16);
    ul.y = (uint32_t)l[2] | ((uint32_t)l[3] << 16);
    *(uint2*)(Hi + i) = uh;
    *(uint2*)(Lo + i) = ul;
}

// W [K,N] fp32 -> transposed split [N,K] bf16 hi/lo
__global__ __launch_bounds__(256)
void conv_w_kernel(const float* __restrict__ W,
                   __nv_bfloat16* __restrict__ Hi,
                   __nv_bfloat16* __restrict__ Lo)
{
    __shared__ float s[32][33];
    const int n0 = blockIdx.x * 32, k0 = blockIdx.y * 32;
    const int tx = threadIdx.x & 31, ty = threadIdx.x >> 5;  // 32 x 8
    #pragma unroll
    for (int i = 0; i < 4; i++)
        s[ty + i * 8][tx] = W[(size_t)(k0 + ty + i * 8) * DM + n0 + tx];
    __syncthreads();
    #pragma unroll
    for (int i = 0; i < 4; i++) {
        float x = s[tx][ty + i * 8];
        __nv_bfloat16 hb = __float2bfloat16(x);
        __nv_bfloat16 lb = __float2bfloat16(x - __bfloat162float(hb));
        const size_t o = (size_t)(n0 + ty + i * 8) * DM + k0 + tx;
        Hi[o] = hb;
        Lo[o] = lb;
    }
}

// ---------------------------------------------------------------------------
// Split-bf16 tensor GEMM via mma.sync:
//   C[M,N] = (Ahi+Alo)[M,K] @ (Whi+Wlo)^T[K,N] + bias  (+ optional elu+1)
// CTA 128x128, 8 warps (warp tile 32x64), BK=64, 2-stage cp.async ring.
// ---------------------------------------------------------------------------
__device__ __forceinline__ void load_chunk(
    const __nv_bfloat16* Ahi, const __nv_bfloat16* Alo,
    const __nv_bfloat16* Bhi, const __nv_bfloat16* Blo,
    int m0, int n0, int tid, int ch, uint32_t stg)
{
    const int r0 = tid >> 3;          // 0..31
    const int c  = tid & 7;           // 16B flit within 128B row
    const uint32_t kbyte = (uint32_t)ch * (KC * 2);
    #pragma unroll
    for (int i = 0; i < 4; i++) {
        const int r = r0 + 32 * i;
        const uint32_t sw = swaddr(0, r, c * 16);
        const size_t ga = (size_t)(m0 + r) * (DM * 2) + kbyte + c * 16;
        const size_t gb = (size_t)(n0 + r) * (DM * 2) + kbyte + c * 16;
        cp16(stg + 0 * TILE_B + sw, (const char*)Ahi + ga);
        cp16(stg + 1 * TILE_B + sw, (const char*)Alo + ga);
        cp16(stg + 2 * TILE_B + sw, (const char*)Bhi + gb);
        cp16(stg + 3 * TILE_B + sw, (const char*)Blo + gb);
    }
}

__global__ __launch_bounds__(256, 1)
void gemm_tc_kernel(const __nv_bfloat16* __restrict__ Ahi,
                    const __nv_bfloat16* __restrict__ Alo,
                    const __nv_bfloat16* __restrict__ Bhi,
                    const __nv_bfloat16* __restrict__ Blo,
                    const float* __restrict__ bias,
                    float* __restrict__ C,
                    int act)
{
    extern __shared__ char smem[];
    const uint32_t sbase = smem_u32(smem);

    const int tid  = threadIdx.x;
    const int wid  = tid >> 5, lane = tid & 31;
    const int wr   = wid & 3;          // warp m-row: m offset wr*32
    const int wc   = wid >> 2;         // warp n-col: n offset wc*64
    const int m0 = blockIdx.y * 128;
    const int n0 = blockIdx.x * 128;

    // ldmatrix lane addressing (shared by A and B patterns)
    const int q   = lane >> 3;
    const int lr  = lane & 7;
    const int rQ  = (q & 1) * 8 + lr;       // row within 16-row tile
    const int kQ  = (q >> 1) * 16;          // byte offset within k16 (16B half)

    float acc[2][8][4];
    #pragma unroll
    for (int mt = 0; mt < 2; mt++)
        #pragma unroll
        for (int nt = 0; nt < 8; nt++)
            #pragma unroll
            for (int e = 0; e < 4; e++) acc[mt][nt][e] = 0.f;

    // prologue
    load_chunk(Ahi, Alo, Bhi, Blo, m0, n0, tid, 0, sbase);
    CP_COMMIT();

    for (int chk = 0; chk < KCHUNKS; chk++) {
        if (chk + 1 < KCHUNKS) {
            load_chunk(Ahi, Alo, Bhi, Blo, m0, n0, tid, chk + 1,
                       sbase + ((chk + 1) & 1) * STG_B);
            CP_COMMIT();
            CP_WAIT1();
        } else {
            CP_WAIT0();
        }
        __syncthreads();

        const uint32_t stg = sbase + (chk & 1) * STG_B;
        const uint32_t tAh = stg + 0 * TILE_B;
        const uint32_t tAl = stg + 1 * TILE_B;
        const uint32_t tBh = stg + 2 * TILE_B;
        const uint32_t tBl = stg + 3 * TILE_B;

        #pragma unroll
        for (int k16 = 0; k16 < 4; k16++) {
            const int kb = k16 * 32 + kQ;
            uint32_t Ah[2][4], Al[2][4], Bh[4][4], Bl[4][4];
            #pragma unroll
            for (int mt = 0; mt < 2; mt++) {
                ldsm4(Ah[mt], swaddr(tAh, wr * 32 + mt * 16 + rQ, kb));
                ldsm4(Al[mt], swaddr(tAl, wr * 32 + mt * 16 + rQ, kb));
            }
            #pragma unroll
            for (int g = 0; g < 4; g++) {
                ldsm4(Bh[g], swaddr(tBh, wc * 64 + g * 16 + rQ, kb));
                ldsm4(Bl[g], swaddr(tBl, wc * 64 + g * 16 + rQ, kb));
            }
            #pragma unroll
            for (int mt = 0; mt < 2; mt++)
                #pragma unroll
                for (int nt = 0; nt < 8; nt++) {
                    const int g = nt >> 1, s = nt & 1;
                    mma16816(acc[mt][nt], Ah[mt], Bh[g][s], Bh[g][s + 2]);
                    mma16816(acc[mt][nt], Ah[mt], Bl[g][s], Bl[g][s + 2]);
                    mma16816(acc[mt][nt], Al[mt], Bh[g][s], Bh[g][s + 2]);
                }
        }
        __syncthreads();
    }

    // epilogue: d0,d1 -> (row, col..col+1); d2,d3 -> (row+8, col..col+1)
    #pragma unroll
    for (int mt = 0; mt < 2; mt++) {
        const int row = m0 + wr * 32 + mt * 16 + (lane >> 2);
        #pragma unroll
        for (int nt = 0; nt < 8; nt++) {
            const int col = n0 + wc * 64 + nt * 8 + 2 * (lane & 3);
            const float b0 = bias[col], b1 = bias[col + 1];
            float v0 = acc[mt][nt][0] + b0;
            float v1 = acc[mt][nt][1] + b1;
            float v2 = acc[mt][nt][2] + b0;
            float v3 = acc[mt][nt][3] + b1;
            if (act) {
                v0 = (v0 > 0.f) ? (v0 + 1.f) : expf(v0);
                v1 = (v1 > 0.f) ? (v1 + 1.f) : expf(v1);
                v2 = (v2 > 0.f) ? (v2 + 1.f) : expf(v2);
                v3 = (v3 > 0.f) ? (v3 + 1.f) : expf(v3);
            }
            *(float2*)(C + (size_t)row * DM + col)       = make_float2(v0, v1);
            *(float2*)(C + (size_t)(row + 8) * DM + col) = make_float2(v2, v3);
        }
    }
}

// ---------------------------------------------------------------------------
// Chunked linear-attention scan (validated in R6, unchanged).
// ---------------------------------------------------------------------------
__global__ __launch_bounds__(256, 2)
void attn_chunk_sums(const float* __restrict__ K,
                     const float* __restrict__ V,
                     float* __restrict__ S,
                     float* __restrict__ Z)
{
    __shared__ float sK[64][64];
    __shared__ float sV[64][64];

    const int ch = blockIdx.x, bh = blockIdx.y;
    const int b = bh >> 4, h = bh & 15;
    const size_t base = (size_t)b * L_ * DM + (size_t)h * HD + (size_t)ch * CH * DM;
    const int tid = threadIdx.x;
    const int tx = tid & 15, ty = tid >> 4;

    #pragma unroll
    for (int it = 0; it < 4; it++) {
        const int r = ty + it * 16;
        *(float4*)&sK[r][tx * 4] = *(const float4*)(K + base + (size_t)r * DM + tx * 4);
        *(float4*)&sV[r][tx * 4] = *(const float4*)(V + base + (size_t)r * DM + tx * 4);
    }
    __syncthreads();

    float acc[4][4];
    #pragma unroll
    for (int i = 0; i < 4; i++)
        #pragma unroll
        for (int j = 0; j < 4; j++) acc[i][j] = 0.f;

    #pragma unroll 4
    for (int j = 0; j < 64; j++) {
        float4 vc = *(const float4*)&sV[j][ty * 4];
        float4 ka = *(const float4*)&sK[j][tx * 4];
        #pragma unroll
        for (int ci = 0; ci < 4; ci++)
            #pragma unroll
            for (int ai = 0; ai < 4; ai++)
                acc[ci][ai] += (&vc.x)[ci] * (&ka.x)[ai];
    }

    float* sout = S + ((size_t)bh * NCH + ch) * (HD * HD);
    #pragma unroll
    for (int ci = 0; ci < 4; ci++)
        *(float4*)(sout + (size_t)(ty * 4 + ci) * HD + tx * 4) =
            make_float4(acc[ci][0], acc[ci][1], acc[ci][2], acc[ci][3]);

    if (tid < 64) {
        float s = 0.f;
        #pragma unroll 8
        for (int j = 0; j < 64; j++) s += sK[j][tid];
        Z[((size_t)bh * NCH + ch) * HD + tid] = s;
    }
}

__global__ __launch_bounds__(512, 1)
void attn_prefix(float* __restrict__ S, float* __restrict__ Z)
{
    const int bh = blockIdx.x;
    const int tid = threadIdx.x;
    const size_t sb = (size_t)bh * NCH * (HD * HD);

    float run[8];
    #pragma unroll
    for (int u = 0; u < 8; u++) run[u] = 0.f;

    for (int ch = 0; ch < NCH; ch++) {
        #pragma unroll
        for (int u = 0; u < 8; u++) {
            const size_t idx = sb + (size_t)ch * (HD * HD) + tid + u * 512;
            float t = S[idx];
            S[idx] = run[u];
            run[u] += t;
        }
    }

    if (tid < 64) {
        const size_t zb = (size_t)bh * NCH * HD;
        float rz = 0.f;
        for (int ch = 0; ch < NCH; ch++) {
            float t = Z[zb + (size_t)ch * HD + tid];
            Z[zb + (size_t)ch * HD + tid] = rz;
            rz += t;
        }
    }
}

__device__ __forceinline__ int skcol(int r, int c) {
    return 4 * (((r >> 2) + c) & 15) + (r & 3);
}

__global__ __launch_bounds__(256, 2)
void attn_chunk_out(const float* __restrict__ Q,
                    const float* __restrict__ K,
                    const float* __restrict__ V,
                    const float* __restrict__ Sp,
                    const float* __restrict__ Zp,
                    float* __restrict__ O)
{
    __shared__ float sQT[64][64];
    __shared__ float sKV[64][64];
    __shared__ float sW[64][64];

    const int ch = blockIdx.x, bh = blockIdx.y;
    const int b = bh >> 4, h = bh & 15;
    const size_t base = (size_t)b * L_ * DM + (size_t)h * HD + (size_t)ch * CH * DM;
    const int tid = threadIdx.x;
    const int tx = tid & 15, ty = tid >> 4;

    #pragma unroll
    for (int it = 0; it < 4; it++) {
        const int r = ty + it * 16;
        float4 qv = *(const float4*)(Q + base + (size_t)r * DM + tx * 4);
        float4 vv = *(const float4*)(V + base + (size_t)r * DM + tx * 4);
        #pragma unroll
        for (int u = 0; u < 4; u++) {
            const int c = tx * 4 + u;
            sQT[c][skcol(r, c)] = (&qv.x)[u];
            sKV[c][skcol(r, c)] = (&vv.x)[u];
        }
    }
    __syncthreads();

    {
        float g[4][4];
        #pragma unroll
        for (int i = 0; i < 4; i++)
            #pragma unroll
            for (int j = 0; j < 4; j++) g[i][j] = 0.f;

        #pragma unroll 4
        for (int c = 0; c < 64; c++) {
            float4 qi = *(const float4*)&sQT[c][4 * ((ty + c) & 15)];
            float4 vj = *(const float4*)&sKV[c][4 * ((tx + c) & 15)];
            #pragma unroll
            for (int ii = 0; ii < 4; ii++)
                #pragma unroll
                for (int jj = 0; jj < 4; jj++)
                    g[ii][jj] += (&qi.x)[ii] * (&vj.x)[jj];
        }
        #pragma unroll
        for (int ii = 0; ii < 4; ii++) {
            const int i = ty * 4 + ii;
            #pragma unroll
            for (int jj = 0; jj < 4; jj++) {
                const int j = tx * 4 + jj;
                sW[i][j] = (j <= i) ? g[ii][jj] : 0.f;
            }
        }
    }
    __syncthreads();

    #pragma unroll
    for (int it = 0; it < 4; it++) {
        const int r = ty + it * 16;
        *(float4*)&sKV[r][tx * 4] = *(const float4*)(K + base + (size_t)r * DM + tx * 4);
    }
    __syncthreads();

    float acc[4][4];
    #pragma unroll
    for (int i = 0; i < 4; i++)
        #pragma unroll
        for (int j = 0; j < 4; j++) acc[i][j] = 0.f;

    #pragma unroll 4
    for (int j = 0; j < 64; j++) {
        float gi[4];
        #pragma unroll
        for (int ii = 0; ii < 4; ii++) gi[ii] = sW[ty * 4 + ii][j];
        float4 ka = *(const float4*)&sKV[j][tx * 4];
        #pragma unroll
        for (int ii = 0; ii < 4; ii++)
            #pragma unroll
            for (int aa = 0; aa < 4; aa++)
                acc[ii][aa] += gi[ii] * (&ka.x)[aa];
    }
    __syncthreads();

    {
        const float* sp = Sp + ((size_t)bh * NCH + ch) * (HD * HD);
        #pragma unroll
        for (int it = 0; it < 4; it++) {
            const int r = ty + it * 16;
            *(float4*)&sW[r][tx * 4] = *(const float4*)(sp + (size_t)r * HD + tx * 4);
        }
    }
    __syncthreads();

    #pragma unroll 4
    for (int c = 0; c < 64; c++) {
        float4 qi = *(const float4*)&sQT[c][4 * ((ty + c) & 15)];
        float4 sa = *(const float4*)&sW[c][tx * 4];
        #pragma unroll
        for (int ii = 0; ii < 4; ii++)
            #pragma unroll
            for (int aa = 0; aa < 4; aa++)
                acc[ii][aa] += (&qi.x)[ii] * (&sa.x)[aa];
    }
    __syncthreads();

    if (tid < 64) {
        const int a = tid;
        float run = Zp[((size_t)bh * NCH + ch) * HD + a];
        for (int i = 0; i < 64; i++) {
            run += sKV[i][a];
            sW[i][a] = run;
        }
    }
    __syncthreads();

    #pragma unroll
    for (int ii = 0; ii < 4; ii++) {
        const int i = ty * 4 + ii;
        float4 z = *(const float4*)&sW[i][tx * 4];
        float o[4];
        #pragma unroll
        for (int aa = 0; aa < 4; aa++) {
            const int a = tx * 4 + aa;
            const float qv = sQT[a][skcol(i, a)];
            o[aa] = acc[ii][aa] / (qv * (&z.x)[aa] + EPSC);
        }
        *(float4*)(O + base + (size_t)i * DM + tx * 4) =
            make_float4(o[0], o[1], o[2], o[3]);
    }
}

// ---------------------------------------------------------------------------
// kernel_launch
// ---------------------------------------------------------------------------
extern "C" void kernel_launch(void* const* d_in, const int* in_sizes, int n_in,
                              void* d_out, int out_size)
{
    const float* queries = (const float*)d_in[0];
    const float* keys    = (const float*)d_in[1];
    const float* values  = (const float*)d_in[2];
    const float* Wq = (const float*)d_in[3];
    const float* bq = (const float*)d_in[4];
    const float* Wk = (const float*)d_in[5];
    const float* bk = (const float*)d_in[6];
    const float* Wv = (const float*)d_in[7];
    const float* bv = (const float*)d_in[8];
    const float* Wo = (const float*)d_in[9];
    const float* bo = (const float*)d_in[10];
    float* out = (float*)d_out;

    float *pQ, *pK, *pV, *pA, *pS, *pZ;
    __nv_bfloat16 *pAhi, *pAlo, *pWhi, *pWlo;
    cudaGetSymbolAddress((void**)&pQ, g_Q);
    cudaGetSymbolAddress((void**)&pK, g_K);
    cudaGetSymbolAddress((void**)&pV, g_V);
    cudaGetSymbolAddress((void**)&pA, g_A);
    cudaGetSymbolAddress((void**)&pS, g_S);
    cudaGetSymbolAddress((void**)&pZ, g_Z);
    cudaGetSymbolAddress((void**)&pAhi, g_Ahi);
    cudaGetSymbolAddress((void**)&pAlo, g_Alo);
    cudaGetSymbolAddress((void**)&pWhi, g_Whi);
    cudaGetSymbolAddress((void**)&pWlo, g_Wlo);

    cudaFuncSetAttribute(gemm_tc_kernel,
                         cudaFuncAttributeMaxDynamicSharedMemorySize, SMEM_GEMM);

    const dim3 ggrid(DM / 128, M_ / 128);           // (8, 64)
    const dim3 cgrid(M_ * DM / (256 * 4));          // conv_split grid
    const dim3 wgrid(DM / 32, DM / 32);             // (32, 32)

    struct { const float *A, *W, *b; float* C; int act; } gm[4] = {
        {queries, Wq, bq, pQ, 1},
        {keys,    Wk, bk, pK, 1},
        {values,  Wv, bv, pV, 0},
        {pA,      Wo, bo, out, 0},
    };

    for (int g = 0; g < 4; g++) {
        if (g == 3) {
            // attention between V-proj and O-proj
            dim3 chunk_grid(NCH, B_ * H_);
            attn_chunk_sums<<<chunk_grid, 256>>>(pK, pV, pS, pZ);
            attn_prefix<<<B_ * H_, 512>>>(pS, pZ);
            attn_chunk_out<<<chunk_grid, 256>>>(pQ, pK, pV, pS, pZ, pA);
        }
        conv_split_kernel<<<cgrid, 256>>>(gm[g].A, pAhi, pAlo);
        conv_w_kernel<<<wgrid, 256>>>(gm[g].W, pWhi, pWlo);
        gemm_tc_kernel<<<ggrid, 256, SMEM_GEMM>>>(pAhi, pAlo, pWhi, pWlo,
                                                  gm[g].b, gm[g].C, gm[g].act);
    }
}

// round 9
// speedup vs baseline: 4.2472x; 1.3913x over previous
#include <cuda_runtime.h>
#include <cuda_fp16.h>
#include <cstdint>
#include <math.h>

// Problem constants
#define B_   4
#define L_   2048
#define DM   1024
#define H_   16
#define HD   64
#define M_   (B_ * L_)       // 8192 rows
#define EPSC 1e-6f
#define CH   64              // scan chunk length
#define NCH  (L_ / CH)       // 32 chunks

// GEMM constants
#define KC        64                  // fp16 K elems per chunk (128 B rows)
#define KCHUNKS   (DM / KC)           // 16
#define TILE_B    16384               // 128-row x 128-byte tile
#define STG_B     (3 * TILE_B)        // A, Bhi, Blo  = 48 KB
#define SMEM_GEMM (2 * STG_B)         // double buffer = 96 KB

// ---------------------------------------------------------------------------
// Scratch (allocation-free rule: __device__ globals)
// ---------------------------------------------------------------------------
__device__ float g_Q[(size_t)M_ * DM];
__device__ float g_K[(size_t)M_ * DM];
__device__ float g_V[(size_t)M_ * DM];
__device__ float g_S[(size_t)B_ * H_ * NCH * HD * HD]; // chunk S sums -> prefix
__device__ float g_Z[(size_t)B_ * H_ * NCH * HD];      // chunk Z sums -> prefix
__device__ __half g_A16[(size_t)M_ * DM];              // fp16 A operand (inputs / attn out)
__device__ __half g_Whi[(size_t)DM * DM];              // [N, K] (transposed W), hi
__device__ __half g_Wlo[(size_t)DM * DM];              // [N, K] lo

// ---------------------------------------------------------------------------
// PTX helpers (base-target sm_103-safe: cp.async, ldmatrix, mma.sync only)
// ---------------------------------------------------------------------------
__device__ __forceinline__ uint32_t smem_u32(const void* p) {
    uint32_t a;
    asm("{ .reg .u64 t; cvta.to.shared.u64 t, %1; cvt.u32.u64 %0, t; }" : "=r"(a) : "l"(p));
    return a;
}
__device__ __forceinline__ void cp16(uint32_t saddr, const void* g) {
    asm volatile("cp.async.cg.shared.global [%0], [%1], 16;\n" :: "r"(saddr), "l"(g));
}
#define CP_COMMIT() asm volatile("cp.async.commit_group;\n")
#define CP_WAIT0()  asm volatile("cp.async.wait_group 0;\n")
#define CP_WAIT1()  asm volatile("cp.async.wait_group 1;\n")

__device__ __forceinline__ void ldsm4(uint32_t* r, uint32_t addr) {
    asm volatile("ldmatrix.sync.aligned.m8n8.x4.shared.b16 {%0,%1,%2,%3}, [%4];"
                 : "=r"(r[0]), "=r"(r[1]), "=r"(r[2]), "=r"(r[3]) : "r"(addr));
}
__device__ __forceinline__ void mma16816(float* d, const uint32_t* a,
                                         uint32_t b0, uint32_t b1) {
    asm volatile(
        "mma.sync.aligned.m16n8k16.row.col.f32.f16.f16.f32 "
        "{%0,%1,%2,%3}, {%4,%5,%6,%7}, {%8,%9}, {%0,%1,%2,%3};"
        : "+f"(d[0]), "+f"(d[1]), "+f"(d[2]), "+f"(d[3])
        : "r"(a[0]), "r"(a[1]), "r"(a[2]), "r"(a[3]), "r"(b0), "r"(b1));
}

// SW128 swizzle address within a 128-row x 128-byte tile
__device__ __forceinline__ uint32_t swaddr(uint32_t tilebase, int row, int cbyte) {
    uint32_t off = ((uint32_t)(row >> 3) << 10) + ((uint32_t)(row & 7) << 7)
                 + (uint32_t)cbyte;
    return tilebase + (off ^ ((off >> 3) & 0x70u));
}

// ---------------------------------------------------------------------------
// Converters
// ---------------------------------------------------------------------------
// fp32 -> fp16 (single), vectorized
__global__ __launch_bounds__(256)
void conv_a_kernel(const float* __restrict__ X, __half* __restrict__ Y)
{
    const size_t i = ((size_t)blockIdx.x * 256 + threadIdx.x) * 4;
    float4 v = *(const float4*)(X + i);
    unsigned short h[4];
    #pragma unroll
    for (int e = 0; e < 4; e++)
        h[e] = __half_as_ushort(__float2half_rn((&v.x)[e]));
    uint2 u;
    u.x = (uint32_t)h[0] | ((uint32_t)h[1] << 16);
    u.y = (uint32_t)h[2] | ((uint32_t)h[3] << 16);
    *(uint2*)(Y + i) = u;
}

// W [K,N] fp32 -> transposed split [N,K] fp16 hi/lo
__global__ __launch_bounds__(256)
void conv_w_kernel(const float* __restrict__ W,
                   __half* __restrict__ Hi,
                   __half* __restrict__ Lo)
{
    __shared__ float s[32][33];
    const int n0 = blockIdx.x * 32, k0 = blockIdx.y * 32;
    const int tx = threadIdx.x & 31, ty = threadIdx.x >> 5;  // 32 x 8
    #pragma unroll
    for (int i = 0; i < 4; i++)
        s[ty + i * 8][tx] = W[(size_t)(k0 + ty + i * 8) * DM + n0 + tx];
    __syncthreads();
    #pragma unroll
    for (int i = 0; i < 4; i++) {
        float x = s[tx][ty + i * 8];
        __half hb = __float2half_rn(x);
        __half lb = __float2half_rn(x - __half2float(hb));
        const size_t o = (size_t)(n0 + ty + i * 8) * DM + k0 + tx;
        Hi[o] = hb;
        Lo[o] = lb;
    }
}

// ---------------------------------------------------------------------------
// 2-pass split-fp16 tensor GEMM:
//   C[M,N] = A16[M,K] @ (Whi+Wlo)^T[K,N] + bias  (+ optional elu+1)
// CTA 128x128, 8 warps (32x64 warp tile), BK=64, 2-stage cp.async ring,
// 96 KB smem -> 2 CTAs/SM.
// ---------------------------------------------------------------------------
__device__ __forceinline__ void load_chunk(
    const __half* A16, const __half* Bhi, const __half* Blo,
    int m0, int n0, int tid, int ch, uint32_t stg)
{
    const int r0 = tid >> 3;          // 0..31
    const int c  = tid & 7;           // 16B flit within 128B row
    const uint32_t kbyte = (uint32_t)ch * (KC * 2);
    #pragma unroll
    for (int i = 0; i < 4; i++) {
        const int r = r0 + 32 * i;
        const uint32_t sw = swaddr(0, r, c * 16);
        const size_t ga = (size_t)(m0 + r) * (DM * 2) + kbyte + c * 16;
        const size_t gb = (size_t)(n0 + r) * (DM * 2) + kbyte + c * 16;
        cp16(stg + 0 * TILE_B + sw, (const char*)A16 + ga);
        cp16(stg + 1 * TILE_B + sw, (const char*)Bhi + gb);
        cp16(stg + 2 * TILE_B + sw, (const char*)Blo + gb);
    }
}

__global__ __launch_bounds__(256, 2)
void gemm_tc_kernel(const __half* __restrict__ A16,
                    const __half* __restrict__ Bhi,
                    const __half* __restrict__ Blo,
                    const float* __restrict__ bias,
                    float* __restrict__ C,
                    int act)
{
    extern __shared__ char smem[];
    const uint32_t sbase = smem_u32(smem);

    const int tid  = threadIdx.x;
    const int wid  = tid >> 5, lane = tid & 31;
    const int wr   = wid & 3;          // warp m-row: m offset wr*32
    const int wc   = wid >> 2;         // warp n-col: n offset wc*64
    const int m0 = blockIdx.y * 128;
    const int n0 = blockIdx.x * 128;

    // ldmatrix lane addressing
    const int q   = lane >> 3;
    const int lr  = lane & 7;
    const int rQ  = (q & 1) * 8 + lr;       // row within 16-row tile
    const int kQ  = (q >> 1) * 16;          // byte offset within k16 (16B half)

    float acc[2][8][4];
    #pragma unroll
    for (int mt = 0; mt < 2; mt++)
        #pragma unroll
        for (int nt = 0; nt < 8; nt++)
            #pragma unroll
            for (int e = 0; e < 4; e++) acc[mt][nt][e] = 0.f;

    // prologue
    load_chunk(A16, Bhi, Blo, m0, n0, tid, 0, sbase);
    CP_COMMIT();

    for (int chk = 0; chk < KCHUNKS; chk++) {
        if (chk + 1 < KCHUNKS) {
            load_chunk(A16, Bhi, Blo, m0, n0, tid, chk + 1,
                       sbase + ((chk + 1) & 1) * STG_B);
            CP_COMMIT();
            CP_WAIT1();
        } else {
            CP_WAIT0();
        }
        __syncthreads();

        const uint32_t stg = sbase + (chk & 1) * STG_B;
        const uint32_t tA  = stg + 0 * TILE_B;
        const uint32_t tBh = stg + 1 * TILE_B;
        const uint32_t tBl = stg + 2 * TILE_B;

        #pragma unroll
        for (int k16 = 0; k16 < 4; k16++) {
            const int kb = k16 * 32 + kQ;
            uint32_t Af[2][4];
            #pragma unroll
            for (int mt = 0; mt < 2; mt++)
                ldsm4(Af[mt], swaddr(tA, wr * 32 + mt * 16 + rQ, kb));
            #pragma unroll
            for (int g = 0; g < 4; g++) {
                uint32_t Bh[4], Bl[4];
                ldsm4(Bh, swaddr(tBh, wc * 64 + g * 16 + rQ, kb));
                ldsm4(Bl, swaddr(tBl, wc * 64 + g * 16 + rQ, kb));
                #pragma unroll
                for (int s = 0; s < 2; s++) {
                    const int nt = g * 2 + s;
                    #pragma unroll
                    for (int mt = 0; mt < 2; mt++) {
                        mma16816(acc[mt][nt], Af[mt], Bh[s], Bh[s + 2]);
                        mma16816(acc[mt][nt], Af[mt], Bl[s], Bl[s + 2]);
                    }
                }
            }
        }
        __syncthreads();
    }

    // epilogue
    #pragma unroll
    for (int mt = 0; mt < 2; mt++) {
        const int row = m0 + wr * 32 + mt * 16 + (lane >> 2);
        #pragma unroll
        for (int nt = 0; nt < 8; nt++) {
            const int col = n0 + wc * 64 + nt * 8 + 2 * (lane & 3);
            const float b0 = bias[col], b1 = bias[col + 1];
            float v0 = acc[mt][nt][0] + b0;
            float v1 = acc[mt][nt][1] + b1;
            float v2 = acc[mt][nt][2] + b0;
            float v3 = acc[mt][nt][3] + b1;
            if (act) {
                v0 = (v0 > 0.f) ? (v0 + 1.f) : expf(v0);
                v1 = (v1 > 0.f) ? (v1 + 1.f) : expf(v1);
                v2 = (v2 > 0.f) ? (v2 + 1.f) : expf(v2);
                v3 = (v3 > 0.f) ? (v3 + 1.f) : expf(v3);
            }
            *(float2*)(C + (size_t)row * DM + col)       = make_float2(v0, v1);
            *(float2*)(C + (size_t)(row + 8) * DM + col) = make_float2(v2, v3);
        }
    }
}

// ---------------------------------------------------------------------------
// Chunked linear-attention scan (validated R6/R8); chunk_out now emits fp16.
// ---------------------------------------------------------------------------
__global__ __launch_bounds__(256, 2)
void attn_chunk_sums(const float* __restrict__ K,
                     const float* __restrict__ V,
                     float* __restrict__ S,
                     float* __restrict__ Z)
{
    __shared__ float sK[64][64];
    __shared__ float sV[64][64];

    const int ch = blockIdx.x, bh = blockIdx.y;
    const int b = bh >> 4, h = bh & 15;
    const size_t base = (size_t)b * L_ * DM + (size_t)h * HD + (size_t)ch * CH * DM;
    const int tid = threadIdx.x;
    const int tx = tid & 15, ty = tid >> 4;

    #pragma unroll
    for (int it = 0; it < 4; it++) {
        const int r = ty + it * 16;
        *(float4*)&sK[r][tx * 4] = *(const float4*)(K + base + (size_t)r * DM + tx * 4);
        *(float4*)&sV[r][tx * 4] = *(const float4*)(V + base + (size_t)r * DM + tx * 4);
    }
    __syncthreads();

    float acc[4][4];
    #pragma unroll
    for (int i = 0; i < 4; i++)
        #pragma unroll
        for (int j = 0; j < 4; j++) acc[i][j] = 0.f;

    #pragma unroll 4
    for (int j = 0; j < 64; j++) {
        float4 vc = *(const float4*)&sV[j][ty * 4];
        float4 ka = *(const float4*)&sK[j][tx * 4];
        #pragma unroll
        for (int ci = 0; ci < 4; ci++)
            #pragma unroll
            for (int ai = 0; ai < 4; ai++)
                acc[ci][ai] += (&vc.x)[ci] * (&ka.x)[ai];
    }

    float* sout = S + ((size_t)bh * NCH + ch) * (HD * HD);
    #pragma unroll
    for (int ci = 0; ci < 4; ci++)
        *(float4*)(sout + (size_t)(ty * 4 + ci) * HD + tx * 4) =
            make_float4(acc[ci][0], acc[ci][1], acc[ci][2], acc[ci][3]);

    if (tid < 64) {
        float s = 0.f;
        #pragma unroll 8
        for (int j = 0; j < 64; j++) s += sK[j][tid];
        Z[((size_t)bh * NCH + ch) * HD + tid] = s;
    }
}

__global__ __launch_bounds__(512, 1)
void attn_prefix(float* __restrict__ S, float* __restrict__ Z)
{
    const int bh = blockIdx.x;
    const int tid = threadIdx.x;
    const size_t sb = (size_t)bh * NCH * (HD * HD);

    float run[8];
    #pragma unroll
    for (int u = 0; u < 8; u++) run[u] = 0.f;

    for (int ch = 0; ch < NCH; ch++) {
        #pragma unroll
        for (int u = 0; u < 8; u++) {
            const size_t idx = sb + (size_t)ch * (HD * HD) + tid + u * 512;
            float t = S[idx];
            S[idx] = run[u];
            run[u] += t;
        }
    }

    if (tid < 64) {
        const size_t zb = (size_t)bh * NCH * HD;
        float rz = 0.f;
        for (int ch = 0; ch < NCH; ch++) {
            float t = Z[zb + (size_t)ch * HD + tid];
            Z[zb + (size_t)ch * HD + tid] = rz;
            rz += t;
        }
    }
}

__device__ __forceinline__ int skcol(int r, int c) {
    return 4 * (((r >> 2) + c) & 15) + (r & 3);
}

__global__ __launch_bounds__(256, 2)
void attn_chunk_out(const float* __restrict__ Q,
                    const float* __restrict__ K,
                    const float* __restrict__ V,
                    const float* __restrict__ Sp,
                    const float* __restrict__ Zp,
                    __half* __restrict__ O16)
{
    __shared__ float sQT[64][64];
    __shared__ float sKV[64][64];
    __shared__ float sW[64][64];

    const int ch = blockIdx.x, bh = blockIdx.y;
    const int b = bh >> 4, h = bh & 15;
    const size_t base = (size_t)b * L_ * DM + (size_t)h * HD + (size_t)ch * CH * DM;
    const int tid = threadIdx.x;
    const int tx = tid & 15, ty = tid >> 4;

    #pragma unroll
    for (int it = 0; it < 4; it++) {
        const int r = ty + it * 16;
        float4 qv = *(const float4*)(Q + base + (size_t)r * DM + tx * 4);
        float4 vv = *(const float4*)(V + base + (size_t)r * DM + tx * 4);
        #pragma unroll
        for (int u = 0; u < 4; u++) {
            const int c = tx * 4 + u;
            sQT[c][skcol(r, c)] = (&qv.x)[u];
            sKV[c][skcol(r, c)] = (&vv.x)[u];
        }
    }
    __syncthreads();

    {
        float g[4][4];
        #pragma unroll
        for (int i = 0; i < 4; i++)
            #pragma unroll
            for (int j = 0; j < 4; j++) g[i][j] = 0.f;

        #pragma unroll 4
        for (int c = 0; c < 64; c++) {
            float4 qi = *(const float4*)&sQT[c][4 * ((ty + c) & 15)];
            float4 vj = *(const float4*)&sKV[c][4 * ((tx + c) & 15)];
            #pragma unroll
            for (int ii = 0; ii < 4; ii++)
                #pragma unroll
                for (int jj = 0; jj < 4; jj++)
                    g[ii][jj] += (&qi.x)[ii] * (&vj.x)[jj];
        }
        #pragma unroll
        for (int ii = 0; ii < 4; ii++) {
            const int i = ty * 4 + ii;
            #pragma unroll
            for (int jj = 0; jj < 4; jj++) {
                const int j = tx * 4 + jj;
                sW[i][j] = (j <= i) ? g[ii][jj] : 0.f;
            }
        }
    }
    __syncthreads();

    #pragma unroll
    for (int it = 0; it < 4; it++) {
        const int r = ty + it * 16;
        *(float4*)&sKV[r][tx * 4] = *(const float4*)(K + base + (size_t)r * DM + tx * 4);
    }
    __syncthreads();

    float acc[4][4];
    #pragma unroll
    for (int i = 0; i < 4; i++)
        #pragma unroll
        for (int j = 0; j < 4; j++) acc[i][j] = 0.f;

    #pragma unroll 4
    for (int j = 0; j < 64; j++) {
        float gi[4];
        #pragma unroll
        for (int ii = 0; ii < 4; ii++) gi[ii] = sW[ty * 4 + ii][j];
        float4 ka = *(const float4*)&sKV[j][tx * 4];
        #pragma unroll
        for (int ii = 0; ii < 4; ii++)
            #pragma unroll
            for (int aa = 0; aa < 4; aa++)
                acc[ii][aa] += gi[ii] * (&ka.x)[aa];
    }
    __syncthreads();

    {
        const float* sp = Sp + ((size_t)bh * NCH + ch) * (HD * HD);
        #pragma unroll
        for (int it = 0; it < 4; it++) {
            const int r = ty + it * 16;
            *(float4*)&sW[r][tx * 4] = *(const float4*)(sp + (size_t)r * HD + tx * 4);
        }
    }
    __syncthreads();

    #pragma unroll 4
    for (int c = 0; c < 64; c++) {
        float4 qi = *(const float4*)&sQT[c][4 * ((ty + c) & 15)];
        float4 sa = *(const float4*)&sW[c][tx * 4];
        #pragma unroll
        for (int ii = 0; ii < 4; ii++)
            #pragma unroll
            for (int aa = 0; aa < 4; aa++)
                acc[ii][aa] += (&qi.x)[ii] * (&sa.x)[aa];
    }
    __syncthreads();

    if (tid < 64) {
        const int a = tid;
        float run = Zp[((size_t)bh * NCH + ch) * HD + a];
        for (int i = 0; i < 64; i++) {
            run += sKV[i][a];
            sW[i][a] = run;
        }
    }
    __syncthreads();

    #pragma unroll
    for (int ii = 0; ii < 4; ii++) {
        const int i = ty * 4 + ii;
        float4 z = *(const float4*)&sW[i][tx * 4];
        unsigned short o[4];
        #pragma unroll
        for (int aa = 0; aa < 4; aa++) {
            const int a = tx * 4 + aa;
            const float qv = sQT[a][skcol(i, a)];
            o[aa] = __half_as_ushort(
                __float2half_rn(acc[ii][aa] / (qv * (&z.x)[aa] + EPSC)));
        }
        uint2 u;
        u.x = (uint32_t)o[0] | ((uint32_t)o[1] << 16);
        u.y = (uint32_t)o[2] | ((uint32_t)o[3] << 16);
        *(uint2*)(O16 + base + (size_t)i * DM + tx * 4) = u;
    }
}

// ---------------------------------------------------------------------------
// kernel_launch
// ---------------------------------------------------------------------------
extern "C" void kernel_launch(void* const* d_in, const int* in_sizes, int n_in,
                              void* d_out, int out_size)
{
    const float* queries = (const float*)d_in[0];
    const float* keys    = (const float*)d_in[1];
    const float* values  = (const float*)d_in[2];
    const float* Wq = (const float*)d_in[3];
    const float* bq = (const float*)d_in[4];
    const float* Wk = (const float*)d_in[5];
    const float* bk = (const float*)d_in[6];
    const float* Wv = (const float*)d_in[7];
    const float* bv = (const float*)d_in[8];
    const float* Wo = (const float*)d_in[9];
    const float* bo = (const float*)d_in[10];
    float* out = (float*)d_out;

    float *pQ, *pK, *pV, *pS, *pZ;
    __half *pA16, *pWhi, *pWlo;
    cudaGetSymbolAddress((void**)&pQ, g_Q);
    cudaGetSymbolAddress((void**)&pK, g_K);
    cudaGetSymbolAddress((void**)&pV, g_V);
    cudaGetSymbolAddress((void**)&pS, g_S);
    cudaGetSymbolAddress((void**)&pZ, g_Z);
    cudaGetSymbolAddress((void**)&pA16, g_A16);
    cudaGetSymbolAddress((void**)&pWhi, g_Whi);
    cudaGetSymbolAddress((void**)&pWlo, g_Wlo);

    cudaFuncSetAttribute(gemm_tc_kernel,
                         cudaFuncAttributeMaxDynamicSharedMemorySize, SMEM_GEMM);

    const dim3 ggrid(DM / 128, M_ / 128);           // (8, 64)
    const dim3 cgrid(M_ * DM / (256 * 4));          // conv_a grid (8192)
    const dim3 wgrid(DM / 32, DM / 32);             // (32, 32)

    struct { const float *A, *W, *b; float* C; int act; } gm[4] = {
        {queries, Wq, bq, pQ, 1},
        {keys,    Wk, bk, pK, 1},
        {values,  Wv, bv, pV, 0},
        {nullptr, Wo, bo, out, 0},   // A comes from scan (fp16, already in g_A16)
    };

    for (int g = 0; g < 4; g++) {
        if (g == 3) {
            // attention between V-proj and O-proj; writes fp16 A directly
            dim3 chunk_grid(NCH, B_ * H_);
            attn_chunk_sums<<<chunk_grid, 256>>>(pK, pV, pS, pZ);
            attn_prefix<<<B_ * H_, 512>>>(pS, pZ);
            attn_chunk_out<<<chunk_grid, 256>>>(pQ, pK, pV, pS, pZ, pA16);
        } else {
            conv_a_kernel<<<cgrid, 256>>>(gm[g].A, pA16);
        }
        conv_w_kernel<<<wgrid, 256>>>(gm[g].W, pWhi, pWlo);
        gemm_tc_kernel<<<ggrid, 256, SMEM_GEMM>>>(pA16, pWhi, pWlo,
                                                  gm[g].b, gm[g].C, gm[g].act);
    }
}

// round 10
// speedup vs baseline: 5.7768x; 1.3601x over previous
#include <cuda_runtime.h>
#include <cuda_fp16.h>
#include <cstdint>
#include <math.h>

// Problem constants
#define B_   4
#define L_   2048
#define DM   1024
#define H_   16
#define HD   64
#define M_   (B_ * L_)       // 8192 rows
#define EPSC 1e-6f
#define CH   64              // scan chunk length
#define NCH  (L_ / CH)       // 32 chunks

// GEMM constants
#define KC        64                  // fp16 K elems per chunk (128 B rows)
#define KCHUNKS   (DM / KC)           // 16
#define TILE_B    16384               // 128-row x 128-byte tile
#define STG_B     (2 * TILE_B)        // A, B  = 32 KB
#define NSTG      3
#define SMEM_GEMM (NSTG * STG_B)      // 96 KB, occ 2

// ---------------------------------------------------------------------------
// Scratch (allocation-free rule: __device__ globals)
// ---------------------------------------------------------------------------
__device__ float g_Q[(size_t)M_ * DM];
__device__ float g_K[(size_t)M_ * DM];
__device__ float g_V[(size_t)M_ * DM];
__device__ float g_S[(size_t)B_ * H_ * NCH * HD * HD]; // chunk S sums -> prefix
__device__ float g_Z[(size_t)B_ * H_ * NCH * HD];      // chunk Z sums -> prefix
__device__ __half g_A16[(size_t)M_ * DM];              // fp16 A operand
__device__ __half g_W16[(size_t)DM * DM];              // [N, K] (transposed W) fp16

// ---------------------------------------------------------------------------
// PTX helpers (base-target sm_103-safe: cp.async, ldmatrix, mma.sync only)
// ---------------------------------------------------------------------------
__device__ __forceinline__ uint32_t smem_u32(const void* p) {
    uint32_t a;
    asm("{ .reg .u64 t; cvta.to.shared.u64 t, %1; cvt.u32.u64 %0, t; }" : "=r"(a) : "l"(p));
    return a;
}
__device__ __forceinline__ void cp16(uint32_t saddr, const void* g) {
    asm volatile("cp.async.cg.shared.global [%0], [%1], 16;\n" :: "r"(saddr), "l"(g));
}
#define CP_COMMIT() asm volatile("cp.async.commit_group;\n")
#define CP_WAIT2()  asm volatile("cp.async.wait_group 2;\n")

__device__ __forceinline__ void ldsm4(uint32_t* r, uint32_t addr) {
    asm volatile("ldmatrix.sync.aligned.m8n8.x4.shared.b16 {%0,%1,%2,%3}, [%4];"
                 : "=r"(r[0]), "=r"(r[1]), "=r"(r[2]), "=r"(r[3]) : "r"(addr));
}
__device__ __forceinline__ void mma16816(float* d, const uint32_t* a,
                                         uint32_t b0, uint32_t b1) {
    asm volatile(
        "mma.sync.aligned.m16n8k16.row.col.f32.f16.f16.f32 "
        "{%0,%1,%2,%3}, {%4,%5,%6,%7}, {%8,%9}, {%0,%1,%2,%3};"
        : "+f"(d[0]), "+f"(d[1]), "+f"(d[2]), "+f"(d[3])
        : "r"(a[0]), "r"(a[1]), "r"(a[2]), "r"(a[3]), "r"(b0), "r"(b1));
}

// SW128 swizzle address within a 128-row x 128-byte tile
__device__ __forceinline__ uint32_t swaddr(uint32_t tilebase, int row, int cbyte) {
    uint32_t off = ((uint32_t)(row >> 3) << 10) + ((uint32_t)(row & 7) << 7)
                 + (uint32_t)cbyte;
    return tilebase + (off ^ ((off >> 3) & 0x70u));
}

// ---------------------------------------------------------------------------
// Converters
// ---------------------------------------------------------------------------
// fp32 -> fp16 (single), vectorized
__global__ __launch_bounds__(256)
void conv_a_kernel(const float* __restrict__ X, __half* __restrict__ Y)
{
    const size_t i = ((size_t)blockIdx.x * 256 + threadIdx.x) * 4;
    float4 v = *(const float4*)(X + i);
    unsigned short h[4];
    #pragma unroll
    for (int e = 0; e < 4; e++)
        h[e] = __half_as_ushort(__float2half_rn((&v.x)[e]));
    uint2 u;
    u.x = (uint32_t)h[0] | ((uint32_t)h[1] << 16);
    u.y = (uint32_t)h[2] | ((uint32_t)h[3] << 16);
    *(uint2*)(Y + i) = u;
}

// W [K,N] fp32 -> transposed [N,K] fp16
__global__ __launch_bounds__(256)
void conv_w_kernel(const float* __restrict__ W, __half* __restrict__ Y)
{
    __shared__ float s[32][33];
    const int n0 = blockIdx.x * 32, k0 = blockIdx.y * 32;
    const int tx = threadIdx.x & 31, ty = threadIdx.x >> 5;  // 32 x 8
    #pragma unroll
    for (int i = 0; i < 4; i++)
        s[ty + i * 8][tx] = W[(size_t)(k0 + ty + i * 8) * DM + n0 + tx];
    __syncthreads();
    #pragma unroll
    for (int i = 0; i < 4; i++) {
        float x = s[tx][ty + i * 8];
        Y[(size_t)(n0 + ty + i * 8) * DM + k0 + tx] = __float2half_rn(x);
    }
}

// ---------------------------------------------------------------------------
// Single-pass fp16 tensor GEMM:
//   C[M,N] = A16[M,K] @ W16^T[K,N] + bias  (+ optional elu+1)
// CTA 128x128, 8 warps (32x64 warp tile), BK=64, 3-stage cp.async ring,
// 96 KB smem -> 2 CTAs/SM.
// ---------------------------------------------------------------------------
__device__ __forceinline__ void load_chunk(
    const __half* A16, const __half* B16,
    int m0, int n0, int tid, int ch, uint32_t stg)
{
    const int r0 = tid >> 3;          // 0..31
    const int c  = tid & 7;           // 16B flit within 128B row
    const uint32_t kbyte = (uint32_t)ch * (KC * 2);
    #pragma unroll
    for (int i = 0; i < 4; i++) {
        const int r = r0 + 32 * i;
        const uint32_t sw = swaddr(0, r, c * 16);
        const size_t ga = (size_t)(m0 + r) * (DM * 2) + kbyte + c * 16;
        const size_t gb = (size_t)(n0 + r) * (DM * 2) + kbyte + c * 16;
        cp16(stg + 0 * TILE_B + sw, (const char*)A16 + ga);
        cp16(stg + 1 * TILE_B + sw, (const char*)B16 + gb);
    }
}

__global__ __launch_bounds__(256, 2)
void gemm_tc_kernel(const __half* __restrict__ A16,
                    const __half* __restrict__ B16,
                    const float* __restrict__ bias,
                    float* __restrict__ C,
                    int act)
{
    extern __shared__ char smem[];
    const uint32_t sbase = smem_u32(smem);

    const int tid  = threadIdx.x;
    const int wid  = tid >> 5, lane = tid & 31;
    const int wr   = wid & 3;          // warp m-row: m offset wr*32
    const int wc   = wid >> 2;         // warp n-col: n offset wc*64
    const int m0 = blockIdx.y * 128;
    const int n0 = blockIdx.x * 128;

    // ldmatrix lane addressing
    const int q   = lane >> 3;
    const int lr  = lane & 7;
    const int rQ  = (q & 1) * 8 + lr;       // row within 16-row tile
    const int kQ  = (q >> 1) * 16;          // byte offset within k16 (16B half)

    float acc[2][8][4];
    #pragma unroll
    for (int mt = 0; mt < 2; mt++)
        #pragma unroll
        for (int nt = 0; nt < 8; nt++)
            #pragma unroll
            for (int e = 0; e < 4; e++) acc[mt][nt][e] = 0.f;

    // prologue: stages 0,1
    load_chunk(A16, B16, m0, n0, tid, 0, sbase + 0 * STG_B);
    CP_COMMIT();
    load_chunk(A16, B16, m0, n0, tid, 1, sbase + 1 * STG_B);
    CP_COMMIT();

    for (int chk = 0; chk < KCHUNKS; chk++) {
        if (chk + 2 < KCHUNKS)
            load_chunk(A16, B16, m0, n0, tid, chk + 2,
                       sbase + ((chk + 2) % NSTG) * STG_B);
        CP_COMMIT();
        CP_WAIT2();           // groups 0..chk complete
        __syncthreads();

        const uint32_t stg = sbase + (chk % NSTG) * STG_B;
        const uint32_t tA  = stg + 0 * TILE_B;
        const uint32_t tB  = stg + 1 * TILE_B;

        #pragma unroll
        for (int k16 = 0; k16 < 4; k16++) {
            const int kb = k16 * 32 + kQ;
            uint32_t Af[2][4];
            #pragma unroll
            for (int mt = 0; mt < 2; mt++)
                ldsm4(Af[mt], swaddr(tA, wr * 32 + mt * 16 + rQ, kb));
            #pragma unroll
            for (int g = 0; g < 4; g++) {
                uint32_t Bf[4];
                ldsm4(Bf, swaddr(tB, wc * 64 + g * 16 + rQ, kb));
                #pragma unroll
                for (int s = 0; s < 2; s++) {
                    const int nt = g * 2 + s;
                    #pragma unroll
                    for (int mt = 0; mt < 2; mt++)
                        mma16816(acc[mt][nt], Af[mt], Bf[s], Bf[s + 2]);
                }
            }
        }
        __syncthreads();   // stage (chk%3) safe to refill at iteration chk+1
    }

    // epilogue
    #pragma unroll
    for (int mt = 0; mt < 2; mt++) {
        const int row = m0 + wr * 32 + mt * 16 + (lane >> 2);
        #pragma unroll
        for (int nt = 0; nt < 8; nt++) {
            const int col = n0 + wc * 64 + nt * 8 + 2 * (lane & 3);
            const float b0 = bias[col], b1 = bias[col + 1];
            float v0 = acc[mt][nt][0] + b0;
            float v1 = acc[mt][nt][1] + b1;
            float v2 = acc[mt][nt][2] + b0;
            float v3 = acc[mt][nt][3] + b1;
            if (act) {
                v0 = (v0 > 0.f) ? (v0 + 1.f) : expf(v0);
                v1 = (v1 > 0.f) ? (v1 + 1.f) : expf(v1);
                v2 = (v2 > 0.f) ? (v2 + 1.f) : expf(v2);
                v3 = (v3 > 0.f) ? (v3 + 1.f) : expf(v3);
            }
            *(float2*)(C + (size_t)row * DM + col)       = make_float2(v0, v1);
            *(float2*)(C + (size_t)(row + 8) * DM + col) = make_float2(v2, v3);
        }
    }
}

// ---------------------------------------------------------------------------
// Chunked linear-attention scan (validated R6/R8/R9); chunk_out emits fp16.
// ---------------------------------------------------------------------------
__global__ __launch_bounds__(256, 2)
void attn_chunk_sums(const float* __restrict__ K,
                     const float* __restrict__ V,
                     float* __restrict__ S,
                     float* __restrict__ Z)
{
    __shared__ float sK[64][64];
    __shared__ float sV[64][64];

    const int ch = blockIdx.x, bh = blockIdx.y;
    const int b = bh >> 4, h = bh & 15;
    const size_t base = (size_t)b * L_ * DM + (size_t)h * HD + (size_t)ch * CH * DM;
    const int tid = threadIdx.x;
    const int tx = tid & 15, ty = tid >> 4;

    #pragma unroll
    for (int it = 0; it < 4; it++) {
        const int r = ty + it * 16;
        *(float4*)&sK[r][tx * 4] = *(const float4*)(K + base + (size_t)r * DM + tx * 4);
        *(float4*)&sV[r][tx * 4] = *(const float4*)(V + base + (size_t)r * DM + tx * 4);
    }
    __syncthreads();

    float acc[4][4];
    #pragma unroll
    for (int i = 0; i < 4; i++)
        #pragma unroll
        for (int j = 0; j < 4; j++) acc[i][j] = 0.f;

    #pragma unroll 4
    for (int j = 0; j < 64; j++) {
        float4 vc = *(const float4*)&sV[j][ty * 4];
        float4 ka = *(const float4*)&sK[j][tx * 4];
        #pragma unroll
        for (int ci = 0; ci < 4; ci++)
            #pragma unroll
            for (int ai = 0; ai < 4; ai++)
                acc[ci][ai] += (&vc.x)[ci] * (&ka.x)[ai];
    }

    float* sout = S + ((size_t)bh * NCH + ch) * (HD * HD);
    #pragma unroll
    for (int ci = 0; ci < 4; ci++)
        *(float4*)(sout + (size_t)(ty * 4 + ci) * HD + tx * 4) =
            make_float4(acc[ci][0], acc[ci][1], acc[ci][2], acc[ci][3]);

    if (tid < 64) {
        float s = 0.f;
        #pragma unroll 8
        for (int j = 0; j < 64; j++) s += sK[j][tid];
        Z[((size_t)bh * NCH + ch) * HD + tid] = s;
    }
}

__global__ __launch_bounds__(512, 1)
void attn_prefix(float* __restrict__ S, float* __restrict__ Z)
{
    const int bh = blockIdx.x;
    const int tid = threadIdx.x;
    const size_t sb = (size_t)bh * NCH * (HD * HD);

    float run[8];
    #pragma unroll
    for (int u = 0; u < 8; u++) run[u] = 0.f;

    for (int ch = 0; ch < NCH; ch++) {
        #pragma unroll
        for (int u = 0; u < 8; u++) {
            const size_t idx = sb + (size_t)ch * (HD * HD) + tid + u * 512;
            float t = S[idx];
            S[idx] = run[u];
            run[u] += t;
        }
    }

    if (tid < 64) {
        const size_t zb = (size_t)bh * NCH * HD;
        float rz = 0.f;
        for (int ch = 0; ch < NCH; ch++) {
            float t = Z[zb + (size_t)ch * HD + tid];
            Z[zb + (size_t)ch * HD + tid] = rz;
            rz += t;
        }
    }
}

__device__ __forceinline__ int skcol(int r, int c) {
    return 4 * (((r >> 2) + c) & 15) + (r & 3);
}

__global__ __launch_bounds__(256, 2)
void attn_chunk_out(const float* __restrict__ Q,
                    const float* __restrict__ K,
                    const float* __restrict__ V,
                    const float* __restrict__ Sp,
                    const float* __restrict__ Zp,
                    __half* __restrict__ O16)
{
    __shared__ float sQT[64][64];
    __shared__ float sKV[64][64];
    __shared__ float sW[64][64];

    const int ch = blockIdx.x, bh = blockIdx.y;
    const int b = bh >> 4, h = bh & 15;
    const size_t base = (size_t)b * L_ * DM + (size_t)h * HD + (size_t)ch * CH * DM;
    const int tid = threadIdx.x;
    const int tx = tid & 15, ty = tid >> 4;

    #pragma unroll
    for (int it = 0; it < 4; it++) {
        const int r = ty + it * 16;
        float4 qv = *(const float4*)(Q + base + (size_t)r * DM + tx * 4);
        float4 vv = *(const float4*)(V + base + (size_t)r * DM + tx * 4);
        #pragma unroll
        for (int u = 0; u < 4; u++) {
            const int c = tx * 4 + u;
            sQT[c][skcol(r, c)] = (&qv.x)[u];
            sKV[c][skcol(r, c)] = (&vv.x)[u];
        }
    }
    __syncthreads();

    {
        float g[4][4];
        #pragma unroll
        for (int i = 0; i < 4; i++)
            #pragma unroll
            for (int j = 0; j < 4; j++) g[i][j] = 0.f;

        #pragma unroll 4
        for (int c = 0; c < 64; c++) {
            float4 qi = *(const float4*)&sQT[c][4 * ((ty + c) & 15)];
            float4 vj = *(const float4*)&sKV[c][4 * ((tx + c) & 15)];
            #pragma unroll
            for (int ii = 0; ii < 4; ii++)
                #pragma unroll
                for (int jj = 0; jj < 4; jj++)
                    g[ii][jj] += (&qi.x)[ii] * (&vj.x)[jj];
        }
        #pragma unroll
        for (int ii = 0; ii < 4; ii++) {
            const int i = ty * 4 + ii;
            #pragma unroll
            for (int jj = 0; jj < 4; jj++) {
                const int j = tx * 4 + jj;
                sW[i][j] = (j <= i) ? g[ii][jj] : 0.f;
            }
        }
    }
    __syncthreads();

    #pragma unroll
    for (int it = 0; it < 4; it++) {
        const int r = ty + it * 16;
        *(float4*)&sKV[r][tx * 4] = *(const float4*)(K + base + (size_t)r * DM + tx * 4);
    }
    __syncthreads();

    float acc[4][4];
    #pragma unroll
    for (int i = 0; i < 4; i++)
        #pragma unroll
        for (int j = 0; j < 4; j++) acc[i][j] = 0.f;

    #pragma unroll 4
    for (int j = 0; j < 64; j++) {
        float gi[4];
        #pragma unroll
        for (int ii = 0; ii < 4; ii++) gi[ii] = sW[ty * 4 + ii][j];
        float4 ka = *(const float4*)&sKV[j][tx * 4];
        #pragma unroll
        for (int ii = 0; ii < 4; ii++)
            #pragma unroll
            for (int aa = 0; aa < 4; aa++)
                acc[ii][aa] += gi[ii] * (&ka.x)[aa];
    }
    __syncthreads();

    {
        const float* sp = Sp + ((size_t)bh * NCH + ch) * (HD * HD);
        #pragma unroll
        for (int it = 0; it < 4; it++) {
            const int r = ty + it * 16;
            *(float4*)&sW[r][tx * 4] = *(const float4*)(sp + (size_t)r * HD + tx * 4);
        }
    }
    __syncthreads();

    #pragma unroll 4
    for (int c = 0; c < 64; c++) {
        float4 qi = *(const float4*)&sQT[c][4 * ((ty + c) & 15)];
        float4 sa = *(const float4*)&sW[c][tx * 4];
        #pragma unroll
        for (int ii = 0; ii < 4; ii++)
            #pragma unroll
            for (int aa = 0; aa < 4; aa++)
                acc[ii][aa] += (&qi.x)[ii] * (&sa.x)[aa];
    }
    __syncthreads();

    if (tid < 64) {
        const int a = tid;
        float run = Zp[((size_t)bh * NCH + ch) * HD + a];
        for (int i = 0; i < 64; i++) {
            run += sKV[i][a];
            sW[i][a] = run;
        }
    }
    __syncthreads();

    #pragma unroll
    for (int ii = 0; ii < 4; ii++) {
        const int i = ty * 4 + ii;
        float4 z = *(const float4*)&sW[i][tx * 4];
        unsigned short o[4];
        #pragma unroll
        for (int aa = 0; aa < 4; aa++) {
            const int a = tx * 4 + aa;
            const float qv = sQT[a][skcol(i, a)];
            o[aa] = __half_as_ushort(
                __float2half_rn(acc[ii][aa] / (qv * (&z.x)[aa] + EPSC)));
        }
        uint2 u;
        u.x = (uint32_t)o[0] | ((uint32_t)o[1] << 16);
        u.y = (uint32_t)o[2] | ((uint32_t)o[3] << 16);
        *(uint2*)(O16 + base + (size_t)i * DM + tx * 4) = u;
    }
}

// ---------------------------------------------------------------------------
// kernel_launch
// ---------------------------------------------------------------------------
extern "C" void kernel_launch(void* const* d_in, const int* in_sizes, int n_in,
                              void* d_out, int out_size)
{
    const float* queries = (const float*)d_in[0];
    const float* keys    = (const float*)d_in[1];
    const float* values  = (const float*)d_in[2];
    const float* Wq = (const float*)d_in[3];
    const float* bq = (const float*)d_in[4];
    const float* Wk = (const float*)d_in[5];
    const float* bk = (const float*)d_in[6];
    const float* Wv = (const float*)d_in[7];
    const float* bv = (const float*)d_in[8];
    const float* Wo = (const float*)d_in[9];
    const float* bo = (const float*)d_in[10];
    float* out = (float*)d_out;

    float *pQ, *pK, *pV, *pS, *pZ;
    __half *pA16, *pW16;
    cudaGetSymbolAddress((void**)&pQ, g_Q);
    cudaGetSymbolAddress((void**)&pK, g_K);
    cudaGetSymbolAddress((void**)&pV, g_V);
    cudaGetSymbolAddress((void**)&pS, g_S);
    cudaGetSymbolAddress((void**)&pZ, g_Z);
    cudaGetSymbolAddress((void**)&pA16, g_A16);
    cudaGetSymbolAddress((void**)&pW16, g_W16);

    cudaFuncSetAttribute(gemm_tc_kernel,
                         cudaFuncAttributeMaxDynamicSharedMemorySize, SMEM_GEMM);

    const dim3 ggrid(DM / 128, M_ / 128);           // (8, 64)
    const dim3 cgrid(M_ * DM / (256 * 4));          // conv_a grid (8192)
    const dim3 wgrid(DM / 32, DM / 32);             // (32, 32)

    struct { const float *A, *W, *b; float* C; int act; } gm[4] = {
        {queries, Wq, bq, pQ, 1},
        {keys,    Wk, bk, pK, 1},
        {values,  Wv, bv, pV, 0},
        {nullptr, Wo, bo, out, 0},   // A comes from scan (fp16, already in g_A16)
    };

    for (int g = 0; g < 4; g++) {
        if (g == 3) {
            // attention between V-proj and O-proj; writes fp16 A directly
            dim3 chunk_grid(NCH, B_ * H_);
            attn_chunk_sums<<<chunk_grid, 256>>>(pK, pV, pS, pZ);
            attn_prefix<<<B_ * H_, 512>>>(pS, pZ);
            attn_chunk_out<<<chunk_grid, 256>>>(pQ, pK, pV, pS, pZ, pA16);
        } else {
            conv_a_kernel<<<cgrid, 256>>>(gm[g].A, pA16);
        }
        conv_w_kernel<<<wgrid, 256>>>(gm[g].W, pW16);
        gemm_tc_kernel<<<ggrid, 256, SMEM_GEMM>>>(pA16, pW16,
                                                  gm[g].b, gm[g].C, gm[g].act);
    }
}